// round 12
// baseline (speedup 1.0000x reference)
#include <cuda_runtime.h>
#include <cuda_fp16.h>
#include <math.h>
#include <cstdint>

#define BATCH 8192
#define EMBED 256
#define HID   256
#define VOCAB 32000

#define KLOG  256    // logits K (single fp16)
#define KGATE 768    // gates K  (single fp16, [c_prev|h_prev|x])

// ============================================================================
// Device scratch (static globals — no runtime allocation)
// ============================================================================
__device__ __half g_Blog[(size_t)VOCAB * KLOG];     // Wl fp16
__device__ __half g_Alog[(size_t)BATCH * KLOG];     // h_t fp16
__device__ __half g_Bgate[(size_t)1024 * KGATE];    // interleaved rows n=4j+g
__device__ __half g_Agate[(size_t)BATCH * KGATE];   // [c,h,x] fp16

// ============================================================================
// PTX helpers (sm_80-era only — safe under .target sm_103)
// ============================================================================
__device__ __forceinline__ uint32_t smem_to_u32(const void* p) {
    uint32_t a;
    asm("{ .reg .u64 t; cvta.to.shared.u64 t, %1; cvt.u32.u64 %0, t; }" : "=r"(a) : "l"(p));
    return a;
}
#define CP_ASYNC16(dst, src) asm volatile("cp.async.cg.shared.global [%0], [%1], 16;" :: "r"(dst), "l"(src) : "memory")
#define CP_COMMIT()  asm volatile("cp.async.commit_group;" ::: "memory")
#define CP_WAIT(N)   asm volatile("cp.async.wait_group %0;" :: "n"(N) : "memory")

#define LDMATRIX_X4(r0, r1, r2, r3, addr) \
    asm volatile("ldmatrix.sync.aligned.m8n8.x4.shared.b16 {%0,%1,%2,%3}, [%4];" \
        : "=r"(r0), "=r"(r1), "=r"(r2), "=r"(r3) : "r"(addr))

#define MMA_F16(d, a, b) \
    asm volatile("mma.sync.aligned.m16n8k16.row.col.f32.f16.f16.f32 " \
        "{%0,%1,%2,%3}, {%4,%5,%6,%7}, {%8,%9}, {%0,%1,%2,%3};" \
        : "+f"((d)[0]), "+f"((d)[1]), "+f"((d)[2]), "+f"((d)[3]) \
        : "r"((a)[0]), "r"((a)[1]), "r"((a)[2]), "r"((a)[3]), \
          "r"((b)[0]), "r"((b)[1]))

__device__ __forceinline__ float sigmoidf_(float v) {
    return 1.0f / (1.0f + expf(-v));
}

// ============================================================================
// Pack kernels (plain fp32 -> fp16 conversion)
// ============================================================================

__global__ __launch_bounds__(256) void pack_B_logits(const float* __restrict__ Wl,
                                                     __half* __restrict__ B)
{
    int i = blockIdx.x * 256 + threadIdx.x;          // float4 index
    if (i >= VOCAB * 256 / 4) return;
    float4 v = ((const float4*)Wl)[i];
    __half2 p0 = __halves2half2(__float2half_rn(v.x), __float2half_rn(v.y));
    __half2 p1 = __halves2half2(__float2half_rn(v.z), __float2half_rn(v.w));
    ((__half2*)B)[i * 2]     = p0;
    ((__half2*)B)[i * 2 + 1] = p1;
}

// Gate weight matrix g_Bgate [1024, 768], INTERLEAVED rows: n = 4*j + g
__global__ __launch_bounds__(256) void pack_B_gates(
    const float* __restrict__ Wf, const float* __restrict__ Wu,
    const float* __restrict__ Wo, const float* __restrict__ Wc,
    __half* __restrict__ B)
{
    int i = blockIdx.x * 256 + threadIdx.x;          // 1024*192 float4 slots
    if (i >= 1024 * 192) return;
    int nidx = i / 192, k4 = (i % 192) * 4;
    int g = nidx >> 8, j = nidx & 255;
    float4 v;
    if (g == 0)      v = ((const float4*)Wf)[(j * 768 + k4) >> 2];
    else if (g == 1) v = ((const float4*)Wu)[(j * 768 + k4) >> 2];
    else if (g == 2) v = ((const float4*)Wo)[(j * 768 + k4) >> 2];
    else {
        if (k4 < 256) v = make_float4(0.f, 0.f, 0.f, 0.f);
        else          v = ((const float4*)Wc)[(j * 512 + (k4 - 256)) >> 2];
    }
    __half2 p0 = __halves2half2(__float2half_rn(v.x), __float2half_rn(v.y));
    __half2 p1 = __halves2half2(__float2half_rn(v.z), __float2half_rn(v.w));
    __half2* d = (__half2*)(B + (size_t)(4 * j + g) * KGATE + k4);
    d[0] = p0; d[1] = p1;
}

// Gate activation matrix g_Agate [8192, 768] = [c_prev, h_prev, x] fp16
__global__ __launch_bounds__(256) void pack_A_gates(
    const float* __restrict__ x, const float* __restrict__ c_prev,
    const float* __restrict__ h_prev, __half* __restrict__ A)
{
    int i = blockIdx.x * 256 + threadIdx.x;          // 8192*192 float4 slots
    if (i >= BATCH * 192) return;
    int b = i / 192, k4 = (i % 192) * 4;
    float4 v;
    if (k4 < 256)       v = ((const float4*)c_prev)[(b * 256 + k4) >> 2];
    else if (k4 < 512)  v = ((const float4*)h_prev)[(b * 256 + (k4 - 256)) >> 2];
    else                v = ((const float4*)x)[(b * 256 + (k4 - 512)) >> 2];
    __half2 p0 = __halves2half2(__float2half_rn(v.x), __float2half_rn(v.y));
    __half2 p1 = __halves2half2(__float2half_rn(v.z), __float2half_rn(v.w));
    __half2* d = (__half2*)(A + (size_t)b * KGATE + k4);
    d[0] = p0; d[1] = p1;
}

// ============================================================================
// fp16 GEMM (fp32 acc):  y[M, ldy] = A[KTOT] . B[KTOT]^T (+bias)
//   BM=128, BN=128, BK=64, 4 warps (2x2), warp tile 64x64, 3-stage cp.async.
//   128 threads/CTA, 110.6 KB smem -> 2 CTAs/SM; fat warp tiles halve
//   LDSM re-read traffic (A x2, B x2) -> MMA-bound instead of smem-bound.
//   EPI=0: y = A.B^T + bias (logits).  EPI=1: fused LSTM combine (gates).
// ============================================================================
#define T_BM 128
#define T_BN 128
#define T_BK 64
#define T_THREADS 128
#define T_LDS 72                         // halfs per smem row (144B)
#define T_ROWS (T_BM + T_BN)             // 256
#define T_STAGE_B (T_ROWS * T_LDS * 2)   // 36864 bytes
#define T_NBUF 3
#define T_SMEM (T_NBUF * T_STAGE_B)      // 110592 bytes
#define EPI_LD 132                       // fp32 staging row stride (floats)

template<int KTOT, int EPI>
__global__ __launch_bounds__(T_THREADS, 2) void gemm_f16(
    const __half* __restrict__ Ag, const __half* __restrict__ Bg,
    const float* __restrict__ bias, float* __restrict__ y, int ldy,
    const float* __restrict__ c_prev,
    const float* __restrict__ bf, const float* __restrict__ bu,
    const float* __restrict__ bo, const float* __restrict__ bc,
    float* __restrict__ c_out, float* __restrict__ h_out,
    __half* __restrict__ alog)
{
    constexpr int NS = KTOT / T_BK;
    static_assert(NS >= 2, "pipeline needs >= 2 stages");
    extern __shared__ char smem[];
    const uint32_t sb = smem_to_u32(smem);
    const int tid  = threadIdx.x;
    const int w    = tid >> 5;
    const int lane = tid & 31;
    const int wr   = (w >> 1) * 64;      // 2 row groups of 64
    const int wc   = (w & 1) * 64;       // 2 col groups of 64
    const int m0   = blockIdx.y * T_BM;
    const int n0   = blockIdx.x * T_BN;

    float acc[4][8][4];
    #pragma unroll
    for (int mf = 0; mf < 4; mf++)
        #pragma unroll
        for (int nf = 0; nf < 8; nf++)
            #pragma unroll
            for (int i = 0; i < 4; i++)
                acc[mf][nf][i] = 0.0f;

    // cp.async addressing: 2048 16B-chunks/stage, 16 per thread
    const int c8 = tid & 7;
    const int r0 = tid >> 3;            // 0..15
    const __half* gA = Ag + (size_t)(m0 + r0) * KTOT + c8 * 8;
    const __half* gB = Bg + (size_t)(n0 + r0) * KTOT + c8 * 8;
    const uint32_t soBase = (uint32_t)(r0 * T_LDS + c8 * 8) * 2;

    auto load_stage = [&](int buf, int k0) {
        uint32_t s0 = sb + buf * T_STAGE_B + soBase;
        #pragma unroll
        for (int it = 0; it < 8; it++)
            CP_ASYNC16(s0 + it * (16 * T_LDS * 2),
                       (const void*)(gA + (size_t)(16 * it) * KTOT + k0));
        s0 += T_BM * T_LDS * 2;
        #pragma unroll
        for (int it = 0; it < 8; it++)
            CP_ASYNC16(s0 + it * (16 * T_LDS * 2),
                       (const void*)(gB + (size_t)(16 * it) * KTOT + k0));
    };

    load_stage(0, 0);        CP_COMMIT();
    load_stage(1, T_BK);     CP_COMMIT();
    CP_WAIT(1);              // stage 0 arrived
    __syncthreads();

    for (int s = 0; s < NS; s++) {
        if (s + 2 < NS) { load_stage((s + 2) % 3, (s + 2) * T_BK); CP_COMMIT(); }

        const uint32_t sA = sb + (s % 3) * T_STAGE_B;
        const uint32_t sB = sA + T_BM * T_LDS * 2;

        #pragma unroll
        for (int ks = 0; ks < 4; ks++) {
            uint32_t a[4][4];
            {
                const int kh = ks * 16 + (lane >> 4) * 8;
                #pragma unroll
                for (int mf = 0; mf < 4; mf++) {
                    int row = wr + mf * 16 + (lane & 15);
                    LDMATRIX_X4(a[mf][0], a[mf][1], a[mf][2], a[mf][3],
                                sA + (uint32_t)(row * T_LDS + kh) * 2);
                }
            }
            uint32_t b[8][2];
            {
                const int kb = ks * 16 + ((lane >> 3) & 1) * 8;
                #pragma unroll
                for (int p = 0; p < 4; p++) {
                    int n = wc + p * 16 + (lane & 7) + ((lane >> 4) & 1) * 8;
                    LDMATRIX_X4(b[2 * p][0], b[2 * p][1],
                                b[2 * p + 1][0], b[2 * p + 1][1],
                                sB + (uint32_t)(n * T_LDS + kb) * 2);
                }
            }
            #pragma unroll
            for (int mf = 0; mf < 4; mf++)
                #pragma unroll
                for (int nf = 0; nf < 8; nf++)
                    MMA_F16(acc[mf][nf], a[mf], b[nf]);
        }

        if (s + 1 < NS) {
            if (s + 2 < NS) CP_WAIT(1);
            else            CP_WAIT(0);
        }
        __syncthreads();
    }

    if (EPI == 0) {
        // logits epilogue: direct float2 stores with bias
        #pragma unroll
        for (int mf = 0; mf < 4; mf++) {
            int r = m0 + wr + mf * 16 + (lane >> 2);
            #pragma unroll
            for (int nf = 0; nf < 8; nf++) {
                int c = n0 + wc + nf * 8 + (lane & 3) * 2;
                float2 bv = *(const float2*)(bias + c);
                float2 v0 = make_float2(acc[mf][nf][0] + bv.x, acc[mf][nf][1] + bv.y);
                float2 v1 = make_float2(acc[mf][nf][2] + bv.x, acc[mf][nf][3] + bv.y);
                *(float2*)(y + (size_t)r * ldy + c)       = v0;
                *(float2*)(y + (size_t)(r + 8) * ldy + c) = v1;
            }
        }
    } else {
        // gates epilogue: stage z-tile (128x128) to smem, combine per unit
        float* stg = (float*)smem;
        #pragma unroll
        for (int mf = 0; mf < 4; mf++) {
            int r = wr + mf * 16 + (lane >> 2);
            #pragma unroll
            for (int nf = 0; nf < 8; nf++) {
                int c = wc + nf * 8 + (lane & 3) * 2;
                *(float2*)(stg + r * EPI_LD + c) =
                    make_float2(acc[mf][nf][0], acc[mf][nf][1]);
                *(float2*)(stg + (r + 8) * EPI_LD + c) =
                    make_float2(acc[mf][nf][2], acc[mf][nf][3]);
            }
        }
        __syncthreads();

        const int j  = tid & 31;          // local unit 0..31
        const int bg = tid >> 5;          // batch group 0..3
        const int jg = (n0 >> 2) + j;     // global unit
        const float bfv = bf[jg], buv = bu[jg], bov = bo[jg], bcv = bc[jg];
        #pragma unroll 4
        for (int bb = 0; bb < 32; bb++) {
            int b  = bg * 32 + bb;
            int bG = m0 + b;
            float4 zv = *(const float4*)(stg + b * EPI_LD + 4 * j);
            float f = sigmoidf_(zv.x + bfv);
            float u = sigmoidf_(zv.y + buv);
            float o = sigmoidf_(zv.z + bov);
            float cn = tanhf(zv.w + bcv);
            float cv = f * c_prev[(size_t)bG * HID + jg] + u * cn;
            float hv = o * tanhf(cv);
            c_out[(size_t)bG * HID + jg] = cv;
            h_out[(size_t)bG * HID + jg] = hv;
            alog[(size_t)bG * KLOG + jg] = __float2half_rn(hv);
        }
    }
}

// ============================================================================
// Launch
// ============================================================================
extern "C" void kernel_launch(void* const* d_in, const int* in_sizes, int n_in,
                              void* d_out, int out_size)
{
    const float* x      = (const float*)d_in[0];
    const float* c_prev = (const float*)d_in[1];
    const float* h_prev = (const float*)d_in[2];
    const float* Wf     = (const float*)d_in[3];
    const float* bf     = (const float*)d_in[4];
    const float* Wu     = (const float*)d_in[5];
    const float* bu     = (const float*)d_in[6];
    const float* Wo     = (const float*)d_in[7];
    const float* bo     = (const float*)d_in[8];
    const float* Wc     = (const float*)d_in[9];
    const float* bc     = (const float*)d_in[10];
    const float* Wl     = (const float*)d_in[11];
    const float* bl     = (const float*)d_in[12];

    float* out   = (float*)d_out;
    float* c_out = out;
    float* h_out = out + (size_t)BATCH * HID;
    float* y_out = out + (size_t)2 * BATCH * HID;

    __half *blog, *alog, *bgate, *agate;
    cudaGetSymbolAddress((void**)&blog,  g_Blog);
    cudaGetSymbolAddress((void**)&alog,  g_Alog);
    cudaGetSymbolAddress((void**)&bgate, g_Bgate);
    cudaGetSymbolAddress((void**)&agate, g_Agate);

    cudaFuncSetAttribute(gemm_f16<KGATE, 1>,
                         cudaFuncAttributeMaxDynamicSharedMemorySize, T_SMEM);
    cudaFuncSetAttribute(gemm_f16<KLOG, 0>,
                         cudaFuncAttributeMaxDynamicSharedMemorySize, T_SMEM);

    // 1) packs
    pack_B_gates<<<(1024 * 192 + 255) / 256, 256>>>(Wf, Wu, Wo, Wc, bgate);
    pack_A_gates<<<(BATCH * 192 + 255) / 256, 256>>>(x, c_prev, h_prev, agate);
    pack_B_logits<<<(VOCAB * 64 + 255) / 256, 256>>>(Wl, blog);

    // 2) gates GEMM with fused LSTM combine -> c_out, h_out, alog
    {
        dim3 g(1024 / T_BN, BATCH / T_BM);   // (8, 64)
        gemm_f16<KGATE, 1><<<g, T_THREADS, T_SMEM>>>(
            agate, bgate, nullptr, nullptr, 0,
            c_prev, bf, bu, bo, bc, c_out, h_out, alog);
    }
    // 3) logits GEMM: y = alog . blog^T + bl   [8192, 32000]
    {
        dim3 g(VOCAB / T_BN, BATCH / T_BM);  // (250, 64)
        gemm_f16<KLOG, 0><<<g, T_THREADS, T_SMEM>>>(
            alog, blog, bl, y_out, VOCAB,
            nullptr, nullptr, nullptr, nullptr, nullptr,
            nullptr, nullptr, nullptr);
    }
}

// round 13
// speedup vs baseline: 1.0833x; 1.0833x over previous
#include <cuda_runtime.h>
#include <cuda_fp16.h>
#include <math.h>
#include <cstdint>

#define BATCH 8192
#define EMBED 256
#define HID   256
#define VOCAB 32000

#define KLOG  256    // logits K (single fp16)
#define KGATE 768    // gates K  (single fp16, [c_prev|h_prev|x])

// ============================================================================
// Device scratch (static globals — no runtime allocation)
// ============================================================================
__device__ __half g_Blog[(size_t)VOCAB * KLOG];     // Wl fp16
__device__ __half g_Alog[(size_t)BATCH * KLOG];     // h_t fp16
__device__ __half g_Bgate[(size_t)1024 * KGATE];    // interleaved rows n=4j+g
__device__ __half g_Agate[(size_t)BATCH * KGATE];   // [c,h,x] fp16

// ============================================================================
// PTX helpers (sm_80-era only — safe under .target sm_103)
// ============================================================================
__device__ __forceinline__ uint32_t smem_to_u32(const void* p) {
    uint32_t a;
    asm("{ .reg .u64 t; cvta.to.shared.u64 t, %1; cvt.u32.u64 %0, t; }" : "=r"(a) : "l"(p));
    return a;
}
#define CP_ASYNC16(dst, src) asm volatile("cp.async.cg.shared.global [%0], [%1], 16;" :: "r"(dst), "l"(src) : "memory")
#define CP_COMMIT()  asm volatile("cp.async.commit_group;" ::: "memory")
#define CP_WAIT(N)   asm volatile("cp.async.wait_group %0;" :: "n"(N) : "memory")

#define LDMATRIX_X4(r0, r1, r2, r3, addr) \
    asm volatile("ldmatrix.sync.aligned.m8n8.x4.shared.b16 {%0,%1,%2,%3}, [%4];" \
        : "=r"(r0), "=r"(r1), "=r"(r2), "=r"(r3) : "r"(addr))

#define MMA_F16(d, a, b) \
    asm volatile("mma.sync.aligned.m16n8k16.row.col.f32.f16.f16.f32 " \
        "{%0,%1,%2,%3}, {%4,%5,%6,%7}, {%8,%9}, {%0,%1,%2,%3};" \
        : "+f"((d)[0]), "+f"((d)[1]), "+f"((d)[2]), "+f"((d)[3]) \
        : "r"((a)[0]), "r"((a)[1]), "r"((a)[2]), "r"((a)[3]), \
          "r"((b)[0]), "r"((b)[1]))

__device__ __forceinline__ float sigmoidf_(float v) {
    return 1.0f / (1.0f + expf(-v));
}

// ============================================================================
// Pack kernels (plain fp32 -> fp16 conversion)
// ============================================================================

__global__ __launch_bounds__(256) void pack_B_logits(const float* __restrict__ Wl,
                                                     __half* __restrict__ B)
{
    int i = blockIdx.x * 256 + threadIdx.x;          // float4 index
    if (i >= VOCAB * 256 / 4) return;
    float4 v = ((const float4*)Wl)[i];
    __half2 p0 = __halves2half2(__float2half_rn(v.x), __float2half_rn(v.y));
    __half2 p1 = __halves2half2(__float2half_rn(v.z), __float2half_rn(v.w));
    ((__half2*)B)[i * 2]     = p0;
    ((__half2*)B)[i * 2 + 1] = p1;
}

// Gate weight matrix g_Bgate [1024, 768], INTERLEAVED rows: n = 4*j + g
__global__ __launch_bounds__(256) void pack_B_gates(
    const float* __restrict__ Wf, const float* __restrict__ Wu,
    const float* __restrict__ Wo, const float* __restrict__ Wc,
    __half* __restrict__ B)
{
    int i = blockIdx.x * 256 + threadIdx.x;          // 1024*192 float4 slots
    if (i >= 1024 * 192) return;
    int nidx = i / 192, k4 = (i % 192) * 4;
    int g = nidx >> 8, j = nidx & 255;
    float4 v;
    if (g == 0)      v = ((const float4*)Wf)[(j * 768 + k4) >> 2];
    else if (g == 1) v = ((const float4*)Wu)[(j * 768 + k4) >> 2];
    else if (g == 2) v = ((const float4*)Wo)[(j * 768 + k4) >> 2];
    else {
        if (k4 < 256) v = make_float4(0.f, 0.f, 0.f, 0.f);
        else          v = ((const float4*)Wc)[(j * 512 + (k4 - 256)) >> 2];
    }
    __half2 p0 = __halves2half2(__float2half_rn(v.x), __float2half_rn(v.y));
    __half2 p1 = __halves2half2(__float2half_rn(v.z), __float2half_rn(v.w));
    __half2* d = (__half2*)(B + (size_t)(4 * j + g) * KGATE + k4);
    d[0] = p0; d[1] = p1;
}

// Gate activation matrix g_Agate [8192, 768] = [c_prev, h_prev, x] fp16
__global__ __launch_bounds__(256) void pack_A_gates(
    const float* __restrict__ x, const float* __restrict__ c_prev,
    const float* __restrict__ h_prev, __half* __restrict__ A)
{
    int i = blockIdx.x * 256 + threadIdx.x;          // 8192*192 float4 slots
    if (i >= BATCH * 192) return;
    int b = i / 192, k4 = (i % 192) * 4;
    float4 v;
    if (k4 < 256)       v = ((const float4*)c_prev)[(b * 256 + k4) >> 2];
    else if (k4 < 512)  v = ((const float4*)h_prev)[(b * 256 + (k4 - 256)) >> 2];
    else                v = ((const float4*)x)[(b * 256 + (k4 - 512)) >> 2];
    __half2 p0 = __halves2half2(__float2half_rn(v.x), __float2half_rn(v.y));
    __half2 p1 = __halves2half2(__float2half_rn(v.z), __float2half_rn(v.w));
    __half2* d = (__half2*)(A + (size_t)b * KGATE + k4);
    d[0] = p0; d[1] = p1;
}

// ============================================================================
// fp16 GEMM (fp32 acc):  y[M, ldy] = A[KTOT] . B[KTOT]^T (+bias)
//   BM=128, BN/NTHREADS templated, BK=64, warp tile 32x64, 3-stage cp.async.
//   Per-warp rotated k-step order de-phases LDSM bursts vs MMA bursts.
//   Logits: BN=128, 256 thr, 2 CTAs/SM.  Gates: BN=256, 512 thr, 1 CTA/SM.
//   EPI=0: y = A.B^T + bias.  EPI=1: fused LSTM combine.
// ============================================================================
#define T_BM 128
#define T_BK 64
#define T_LDS 72                         // halfs per smem row (144B)

template<int KTOT, int BN, int NTHREADS, int MINCTA, int EPI>
__global__ __launch_bounds__(NTHREADS, MINCTA) void gemm_f16(
    const __half* __restrict__ Ag, const __half* __restrict__ Bg,
    const float* __restrict__ bias, float* __restrict__ y, int ldy,
    const float* __restrict__ c_prev,
    const float* __restrict__ bf, const float* __restrict__ bu,
    const float* __restrict__ bo, const float* __restrict__ bc,
    float* __restrict__ c_out, float* __restrict__ h_out,
    __half* __restrict__ alog)
{
    constexpr int NS      = KTOT / T_BK;
    constexpr int NWARPS  = NTHREADS / 32;
    constexpr int WARPS_N = BN / 64;
    constexpr int WARPS_M = NWARPS / WARPS_N;      // 4 in both configs
    constexpr int ROWS    = T_BM + BN;
    constexpr int STAGE_B = ROWS * T_LDS * 2;
    constexpr int RSTEP   = NTHREADS / 8;          // rows per cp.async sweep
    constexpr int EPI_LD  = BN + 4;
    static_assert(NS >= 2, "pipeline needs >= 2 stages");

    extern __shared__ char smem[];
    const uint32_t sb = smem_to_u32(smem);
    const int tid  = threadIdx.x;
    const int w    = tid >> 5;
    const int lane = tid & 31;
    const int wr   = (w % WARPS_M) * 32;
    const int wc   = (w / WARPS_M) * 64;
    const int m0   = blockIdx.y * T_BM;
    const int n0   = blockIdx.x * BN;

    float acc[2][8][4];
    #pragma unroll
    for (int mf = 0; mf < 2; mf++)
        #pragma unroll
        for (int nf = 0; nf < 8; nf++)
            #pragma unroll
            for (int i = 0; i < 4; i++)
                acc[mf][nf][i] = 0.0f;

    // cp.async addressing
    const int c8 = tid & 7;
    const int r0 = tid >> 3;
    const __half* gA = Ag + (size_t)(m0 + r0) * KTOT + c8 * 8;
    const __half* gB = Bg + (size_t)(n0 + r0) * KTOT + c8 * 8;
    const uint32_t soBase = (uint32_t)(r0 * T_LDS + c8 * 8) * 2;

    auto load_stage = [&](int buf, int k0) {
        uint32_t s0 = sb + buf * STAGE_B + soBase;
        #pragma unroll
        for (int it = 0; it < T_BM / RSTEP; it++)
            CP_ASYNC16(s0 + it * (RSTEP * T_LDS * 2),
                       (const void*)(gA + (size_t)(RSTEP * it) * KTOT + k0));
        s0 += T_BM * T_LDS * 2;
        #pragma unroll
        for (int it = 0; it < BN / RSTEP; it++)
            CP_ASYNC16(s0 + it * (RSTEP * T_LDS * 2),
                       (const void*)(gB + (size_t)(RSTEP * it) * KTOT + k0));
    };

    load_stage(0, 0);        CP_COMMIT();
    load_stage(1, T_BK);     CP_COMMIT();
    CP_WAIT(1);              // stage 0 arrived
    __syncthreads();

    for (int s = 0; s < NS; s++) {
        if (s + 2 < NS) { load_stage((s + 2) % 3, (s + 2) * T_BK); CP_COMMIT(); }

        const uint32_t sA = sb + (s % 3) * STAGE_B;
        const uint32_t sB = sA + T_BM * T_LDS * 2;

        #pragma unroll
        for (int kk = 0; kk < 4; kk++) {
            const int ks = (kk + w) & 3;    // per-warp rotated k order
            uint32_t a[2][4];
            {
                const int kh = ks * 16 + (lane >> 4) * 8;
                #pragma unroll
                for (int mf = 0; mf < 2; mf++) {
                    int row = wr + mf * 16 + (lane & 15);
                    LDMATRIX_X4(a[mf][0], a[mf][1], a[mf][2], a[mf][3],
                                sA + (uint32_t)(row * T_LDS + kh) * 2);
                }
            }
            uint32_t b[8][2];
            {
                const int kb = ks * 16 + ((lane >> 3) & 1) * 8;
                #pragma unroll
                for (int p = 0; p < 4; p++) {
                    int n = wc + p * 16 + (lane & 7) + ((lane >> 4) & 1) * 8;
                    LDMATRIX_X4(b[2 * p][0], b[2 * p][1],
                                b[2 * p + 1][0], b[2 * p + 1][1],
                                sB + (uint32_t)(n * T_LDS + kb) * 2);
                }
            }
            #pragma unroll
            for (int mf = 0; mf < 2; mf++)
                #pragma unroll
                for (int nf = 0; nf < 8; nf++)
                    MMA_F16(acc[mf][nf], a[mf], b[nf]);
        }

        if (s + 1 < NS) {
            if (s + 2 < NS) CP_WAIT(1);
            else            CP_WAIT(0);
        }
        __syncthreads();
    }

    if (EPI == 0) {
        // logits epilogue: direct float2 stores with bias
        #pragma unroll
        for (int mf = 0; mf < 2; mf++) {
            int r = m0 + wr + mf * 16 + (lane >> 2);
            #pragma unroll
            for (int nf = 0; nf < 8; nf++) {
                int c = n0 + wc + nf * 8 + (lane & 3) * 2;
                float2 bv = *(const float2*)(bias + c);
                float2 v0 = make_float2(acc[mf][nf][0] + bv.x, acc[mf][nf][1] + bv.y);
                float2 v1 = make_float2(acc[mf][nf][2] + bv.x, acc[mf][nf][3] + bv.y);
                *(float2*)(y + (size_t)r * ldy + c)       = v0;
                *(float2*)(y + (size_t)(r + 8) * ldy + c) = v1;
            }
        }
    } else {
        // gates epilogue: stage z-tile (128 x BN) to smem, combine per unit
        float* stg = (float*)smem;
        #pragma unroll
        for (int mf = 0; mf < 2; mf++) {
            int r = wr + mf * 16 + (lane >> 2);
            #pragma unroll
            for (int nf = 0; nf < 8; nf++) {
                int c = wc + nf * 8 + (lane & 3) * 2;
                *(float2*)(stg + r * EPI_LD + c) =
                    make_float2(acc[mf][nf][0], acc[mf][nf][1]);
                *(float2*)(stg + (r + 8) * EPI_LD + c) =
                    make_float2(acc[mf][nf][2], acc[mf][nf][3]);
            }
        }
        __syncthreads();

        constexpr int JW   = BN / 4;              // units per tile
        constexpr int NBG  = NTHREADS / JW;       // batch groups
        constexpr int RPT  = T_BM / NBG;          // rows per thread
        const int j  = tid % JW;
        const int bg = tid / JW;
        const int jg = (n0 >> 2) + j;
        const float bfv = bf[jg], buv = bu[jg], bov = bo[jg], bcv = bc[jg];
        #pragma unroll 4
        for (int bb = 0; bb < RPT; bb++) {
            int b  = bg * RPT + bb;
            int bG = m0 + b;
            float4 zv = *(const float4*)(stg + b * EPI_LD + 4 * j);
            float f = sigmoidf_(zv.x + bfv);
            float u = sigmoidf_(zv.y + buv);
            float o = sigmoidf_(zv.z + bov);
            float cn = tanhf(zv.w + bcv);
            float cv = f * c_prev[(size_t)bG * HID + jg] + u * cn;
            float hv = o * tanhf(cv);
            c_out[(size_t)bG * HID + jg] = cv;
            h_out[(size_t)bG * HID + jg] = hv;
            alog[(size_t)bG * KLOG + jg] = __float2half_rn(hv);
        }
    }
}

// ============================================================================
// Launch
// ============================================================================
extern "C" void kernel_launch(void* const* d_in, const int* in_sizes, int n_in,
                              void* d_out, int out_size)
{
    const float* x      = (const float*)d_in[0];
    const float* c_prev = (const float*)d_in[1];
    const float* h_prev = (const float*)d_in[2];
    const float* Wf     = (const float*)d_in[3];
    const float* bf     = (const float*)d_in[4];
    const float* Wu     = (const float*)d_in[5];
    const float* bu     = (const float*)d_in[6];
    const float* Wo     = (const float*)d_in[7];
    const float* bo     = (const float*)d_in[8];
    const float* Wc     = (const float*)d_in[9];
    const float* bc     = (const float*)d_in[10];
    const float* Wl     = (const float*)d_in[11];
    const float* bl     = (const float*)d_in[12];

    float* out   = (float*)d_out;
    float* c_out = out;
    float* h_out = out + (size_t)BATCH * HID;
    float* y_out = out + (size_t)2 * BATCH * HID;

    __half *blog, *alog, *bgate, *agate;
    cudaGetSymbolAddress((void**)&blog,  g_Blog);
    cudaGetSymbolAddress((void**)&alog,  g_Alog);
    cudaGetSymbolAddress((void**)&bgate, g_Bgate);
    cudaGetSymbolAddress((void**)&agate, g_Agate);

    // gates: BN=256, 512 threads, 1 CTA/SM, smem (128+256)*144*3 = 165888
    constexpr int SMEM_G = (128 + 256) * 144 * 3;
    // logits: BN=128, 256 threads, 2 CTAs/SM, smem (128+128)*144*3 = 110592
    constexpr int SMEM_L = (128 + 128) * 144 * 3;

    cudaFuncSetAttribute((const void*)gemm_f16<KGATE, 256, 512, 1, 1>,
                         cudaFuncAttributeMaxDynamicSharedMemorySize, SMEM_G);
    cudaFuncSetAttribute((const void*)gemm_f16<KLOG, 128, 256, 2, 0>,
                         cudaFuncAttributeMaxDynamicSharedMemorySize, SMEM_L);

    // 1) packs
    pack_B_gates<<<(1024 * 192 + 255) / 256, 256>>>(Wf, Wu, Wo, Wc, bgate);
    pack_A_gates<<<(BATCH * 192 + 255) / 256, 256>>>(x, c_prev, h_prev, agate);
    pack_B_logits<<<(VOCAB * 64 + 255) / 256, 256>>>(Wl, blog);

    // 2) gates GEMM with fused LSTM combine -> c_out, h_out, alog
    {
        dim3 g(1024 / 256, BATCH / T_BM);    // (4, 64)
        gemm_f16<KGATE, 256, 512, 1, 1><<<g, 512, SMEM_G>>>(
            agate, bgate, nullptr, nullptr, 0,
            c_prev, bf, bu, bo, bc, c_out, h_out, alog);
    }
    // 3) logits GEMM: y = alog . blog^T + bl   [8192, 32000]
    {
        dim3 g(VOCAB / 128, BATCH / T_BM);   // (250, 64)
        gemm_f16<KLOG, 128, 256, 2, 0><<<g, 256, SMEM_L>>>(
            alog, blog, bl, y_out, VOCAB,
            nullptr, nullptr, nullptr, nullptr, nullptr,
            nullptr, nullptr, nullptr);
    }
}

// round 14
// speedup vs baseline: 1.1251x; 1.0385x over previous
#include <cuda_runtime.h>
#include <cuda_fp16.h>
#include <math.h>
#include <cstdint>

#define BATCH 8192
#define EMBED 256
#define HID   256
#define VOCAB 32000

#define KLOG  256    // logits K (single fp16)
#define KGATE 768    // gates K  (single fp16, [c_prev|h_prev|x])

// ============================================================================
// Device scratch (static globals — no runtime allocation)
// ============================================================================
__device__ __half g_Blog[(size_t)VOCAB * KLOG];     // Wl fp16
__device__ __half g_Alog[(size_t)BATCH * KLOG];     // h_t fp16
__device__ __half g_Bgate[(size_t)1024 * KGATE];    // interleaved rows n=4j+g
__device__ __half g_Agate[(size_t)BATCH * KGATE];   // [c,h,x] fp16

// ============================================================================
// PTX helpers (sm_80-era only — safe under .target sm_103)
// ============================================================================
__device__ __forceinline__ uint32_t smem_to_u32(const void* p) {
    uint32_t a;
    asm("{ .reg .u64 t; cvta.to.shared.u64 t, %1; cvt.u32.u64 %0, t; }" : "=r"(a) : "l"(p));
    return a;
}
#define CP_ASYNC16(dst, src) asm volatile("cp.async.cg.shared.global [%0], [%1], 16;" :: "r"(dst), "l"(src) : "memory")
#define CP_COMMIT()  asm volatile("cp.async.commit_group;" ::: "memory")
#define CP_WAIT(N)   asm volatile("cp.async.wait_group %0;" :: "n"(N) : "memory")

#define LDMATRIX_X4(r0, r1, r2, r3, addr) \
    asm volatile("ldmatrix.sync.aligned.m8n8.x4.shared.b16 {%0,%1,%2,%3}, [%4];" \
        : "=r"(r0), "=r"(r1), "=r"(r2), "=r"(r3) : "r"(addr))

#define MMA_F16(d, a, b) \
    asm volatile("mma.sync.aligned.m16n8k16.row.col.f32.f16.f16.f32 " \
        "{%0,%1,%2,%3}, {%4,%5,%6,%7}, {%8,%9}, {%0,%1,%2,%3};" \
        : "+f"((d)[0]), "+f"((d)[1]), "+f"((d)[2]), "+f"((d)[3]) \
        : "r"((a)[0]), "r"((a)[1]), "r"((a)[2]), "r"((a)[3]), \
          "r"((b)[0]), "r"((b)[1]))

// fast-math activations (rel err ~2^-21, negligible vs fp16 GEMM error)
__device__ __forceinline__ float fsig(float x) {
    return __fdividef(1.0f, 1.0f + __expf(-x));
}
__device__ __forceinline__ float ftanh_(float x) {
    float e = __expf(fminf(fmaxf(2.0f * x, -30.0f), 30.0f));
    return __fdividef(e - 1.0f, e + 1.0f);
}

// ============================================================================
// Merged pack kernel: Bgate + Agate + Blog in one launch (flat float4 index)
// ============================================================================
#define PK_BG (1024 * 192)               // Bgate float4 slots
#define PK_AG (BATCH * 192)              // Agate float4 slots
#define PK_BL (VOCAB * 64)               // Blog float4 slots
#define PK_TOTAL (PK_BG + PK_AG + PK_BL)

__global__ __launch_bounds__(256) void pack_all(
    const float* __restrict__ Wf, const float* __restrict__ Wu,
    const float* __restrict__ Wo, const float* __restrict__ Wc,
    const float* __restrict__ x, const float* __restrict__ c_prev,
    const float* __restrict__ h_prev, const float* __restrict__ Wl,
    __half* __restrict__ Bgate, __half* __restrict__ Agate,
    __half* __restrict__ Blog)
{
    int i = blockIdx.x * 256 + threadIdx.x;
    if (i >= PK_TOTAL) return;

    if (i < PK_BG) {
        // Bgate [1024,768], interleaved rows n=4j+g, k=[c_prev|h_prev|x]
        int nidx = i / 192, k4 = (i % 192) * 4;
        int g = nidx >> 8, j = nidx & 255;
        float4 v;
        if (g == 0)      v = ((const float4*)Wf)[(j * 768 + k4) >> 2];
        else if (g == 1) v = ((const float4*)Wu)[(j * 768 + k4) >> 2];
        else if (g == 2) v = ((const float4*)Wo)[(j * 768 + k4) >> 2];
        else {
            if (k4 < 256) v = make_float4(0.f, 0.f, 0.f, 0.f);
            else          v = ((const float4*)Wc)[(j * 512 + (k4 - 256)) >> 2];
        }
        __half2 p0 = __halves2half2(__float2half_rn(v.x), __float2half_rn(v.y));
        __half2 p1 = __halves2half2(__float2half_rn(v.z), __float2half_rn(v.w));
        __half2* d = (__half2*)(Bgate + (size_t)(4 * j + g) * KGATE + k4);
        d[0] = p0; d[1] = p1;
    } else if (i < PK_BG + PK_AG) {
        // Agate [8192,768] = [c_prev, h_prev, x]
        int t = i - PK_BG;
        int b = t / 192, k4 = (t % 192) * 4;
        float4 v;
        if (k4 < 256)       v = ((const float4*)c_prev)[(b * 256 + k4) >> 2];
        else if (k4 < 512)  v = ((const float4*)h_prev)[(b * 256 + (k4 - 256)) >> 2];
        else                v = ((const float4*)x)[(b * 256 + (k4 - 512)) >> 2];
        __half2 p0 = __halves2half2(__float2half_rn(v.x), __float2half_rn(v.y));
        __half2 p1 = __halves2half2(__float2half_rn(v.z), __float2half_rn(v.w));
        __half2* d = (__half2*)(Agate + (size_t)b * KGATE + k4);
        d[0] = p0; d[1] = p1;
    } else {
        // Blog: plain Wl fp32 -> fp16
        int t = i - PK_BG - PK_AG;
        float4 v = ((const float4*)Wl)[t];
        __half2 p0 = __halves2half2(__float2half_rn(v.x), __float2half_rn(v.y));
        __half2 p1 = __halves2half2(__float2half_rn(v.z), __float2half_rn(v.w));
        ((__half2*)Blog)[t * 2]     = p0;
        ((__half2*)Blog)[t * 2 + 1] = p1;
    }
}

// ============================================================================
// fp16 GEMM (fp32 acc):  y[M, ldy] = A[KTOT] . B[KTOT]^T (+bias)
//   BM=128, BN/NTHREADS templated, BK=64, warp tile 32x64, 3-stage cp.async.
//   Per-warp rotated k-step order de-phases LDSM bursts vs MMA bursts.
//   Logits: BN=128, 256 thr, 2 CTAs/SM.  Gates: BN=256, 512 thr, 1 CTA/SM.
//   EPI=0: y = A.B^T + bias.  EPI=1: fused LSTM combine (fast-math).
// ============================================================================
#define T_BM 128
#define T_BK 64
#define T_LDS 72                         // halfs per smem row (144B)

template<int KTOT, int BN, int NTHREADS, int MINCTA, int EPI>
__global__ __launch_bounds__(NTHREADS, MINCTA) void gemm_f16(
    const __half* __restrict__ Ag, const __half* __restrict__ Bg,
    const float* __restrict__ bias, float* __restrict__ y, int ldy,
    const float* __restrict__ c_prev,
    const float* __restrict__ bf, const float* __restrict__ bu,
    const float* __restrict__ bo, const float* __restrict__ bc,
    float* __restrict__ c_out, float* __restrict__ h_out,
    __half* __restrict__ alog)
{
    constexpr int NS      = KTOT / T_BK;
    constexpr int NWARPS  = NTHREADS / 32;
    constexpr int WARPS_N = BN / 64;
    constexpr int WARPS_M = NWARPS / WARPS_N;      // 4 in both configs
    constexpr int ROWS    = T_BM + BN;
    constexpr int STAGE_B = ROWS * T_LDS * 2;
    constexpr int RSTEP   = NTHREADS / 8;          // rows per cp.async sweep
    constexpr int EPI_LD  = BN + 4;
    static_assert(NS >= 2, "pipeline needs >= 2 stages");

    extern __shared__ char smem[];
    const uint32_t sb = smem_to_u32(smem);
    const int tid  = threadIdx.x;
    const int w    = tid >> 5;
    const int lane = tid & 31;
    const int wr   = (w % WARPS_M) * 32;
    const int wc   = (w / WARPS_M) * 64;
    const int m0   = blockIdx.y * T_BM;
    const int n0   = blockIdx.x * BN;

    float acc[2][8][4];
    #pragma unroll
    for (int mf = 0; mf < 2; mf++)
        #pragma unroll
        for (int nf = 0; nf < 8; nf++)
            #pragma unroll
            for (int i = 0; i < 4; i++)
                acc[mf][nf][i] = 0.0f;

    // cp.async addressing
    const int c8 = tid & 7;
    const int r0 = tid >> 3;
    const __half* gA = Ag + (size_t)(m0 + r0) * KTOT + c8 * 8;
    const __half* gB = Bg + (size_t)(n0 + r0) * KTOT + c8 * 8;
    const uint32_t soBase = (uint32_t)(r0 * T_LDS + c8 * 8) * 2;

    auto load_stage = [&](int buf, int k0) {
        uint32_t s0 = sb + buf * STAGE_B + soBase;
        #pragma unroll
        for (int it = 0; it < T_BM / RSTEP; it++)
            CP_ASYNC16(s0 + it * (RSTEP * T_LDS * 2),
                       (const void*)(gA + (size_t)(RSTEP * it) * KTOT + k0));
        s0 += T_BM * T_LDS * 2;
        #pragma unroll
        for (int it = 0; it < BN / RSTEP; it++)
            CP_ASYNC16(s0 + it * (RSTEP * T_LDS * 2),
                       (const void*)(gB + (size_t)(RSTEP * it) * KTOT + k0));
    };

    load_stage(0, 0);        CP_COMMIT();
    load_stage(1, T_BK);     CP_COMMIT();
    CP_WAIT(1);              // stage 0 arrived
    __syncthreads();

    for (int s = 0; s < NS; s++) {
        if (s + 2 < NS) { load_stage((s + 2) % 3, (s + 2) * T_BK); CP_COMMIT(); }

        const uint32_t sA = sb + (s % 3) * STAGE_B;
        const uint32_t sB = sA + T_BM * T_LDS * 2;

        #pragma unroll
        for (int kk = 0; kk < 4; kk++) {
            const int ks = (kk + w) & 3;    // per-warp rotated k order
            uint32_t a[2][4];
            {
                const int kh = ks * 16 + (lane >> 4) * 8;
                #pragma unroll
                for (int mf = 0; mf < 2; mf++) {
                    int row = wr + mf * 16 + (lane & 15);
                    LDMATRIX_X4(a[mf][0], a[mf][1], a[mf][2], a[mf][3],
                                sA + (uint32_t)(row * T_LDS + kh) * 2);
                }
            }
            uint32_t b[8][2];
            {
                const int kb = ks * 16 + ((lane >> 3) & 1) * 8;
                #pragma unroll
                for (int p = 0; p < 4; p++) {
                    int n = wc + p * 16 + (lane & 7) + ((lane >> 4) & 1) * 8;
                    LDMATRIX_X4(b[2 * p][0], b[2 * p][1],
                                b[2 * p + 1][0], b[2 * p + 1][1],
                                sB + (uint32_t)(n * T_LDS + kb) * 2);
                }
            }
            #pragma unroll
            for (int mf = 0; mf < 2; mf++)
                #pragma unroll
                for (int nf = 0; nf < 8; nf++)
                    MMA_F16(acc[mf][nf], a[mf], b[nf]);
        }

        if (s + 1 < NS) {
            if (s + 2 < NS) CP_WAIT(1);
            else            CP_WAIT(0);
        }
        __syncthreads();
    }

    if (EPI == 0) {
        // logits epilogue: direct float2 stores with bias
        #pragma unroll
        for (int mf = 0; mf < 2; mf++) {
            int r = m0 + wr + mf * 16 + (lane >> 2);
            #pragma unroll
            for (int nf = 0; nf < 8; nf++) {
                int c = n0 + wc + nf * 8 + (lane & 3) * 2;
                float2 bv = *(const float2*)(bias + c);
                float2 v0 = make_float2(acc[mf][nf][0] + bv.x, acc[mf][nf][1] + bv.y);
                float2 v1 = make_float2(acc[mf][nf][2] + bv.x, acc[mf][nf][3] + bv.y);
                *(float2*)(y + (size_t)r * ldy + c)       = v0;
                *(float2*)(y + (size_t)(r + 8) * ldy + c) = v1;
            }
        }
    } else {
        // gates epilogue: stage z-tile (128 x BN) to smem, combine per unit
        float* stg = (float*)smem;
        #pragma unroll
        for (int mf = 0; mf < 2; mf++) {
            int r = wr + mf * 16 + (lane >> 2);
            #pragma unroll
            for (int nf = 0; nf < 8; nf++) {
                int c = wc + nf * 8 + (lane & 3) * 2;
                *(float2*)(stg + r * EPI_LD + c) =
                    make_float2(acc[mf][nf][0], acc[mf][nf][1]);
                *(float2*)(stg + (r + 8) * EPI_LD + c) =
                    make_float2(acc[mf][nf][2], acc[mf][nf][3]);
            }
        }
        __syncthreads();

        constexpr int JW   = BN / 4;              // units per tile
        constexpr int NBG  = NTHREADS / JW;       // batch groups
        constexpr int RPT  = T_BM / NBG;          // rows per thread
        const int j  = tid % JW;
        const int bg = tid / JW;
        const int jg = (n0 >> 2) + j;
        const float bfv = bf[jg], buv = bu[jg], bov = bo[jg], bcv = bc[jg];
        #pragma unroll 4
        for (int bb = 0; bb < RPT; bb++) {
            int b  = bg * RPT + bb;
            int bG = m0 + b;
            float4 zv = *(const float4*)(stg + b * EPI_LD + 4 * j);
            float f  = fsig(zv.x + bfv);
            float u  = fsig(zv.y + buv);
            float o  = fsig(zv.z + bov);
            float cn = ftanh_(zv.w + bcv);
            float cv = f * c_prev[(size_t)bG * HID + jg] + u * cn;
            float hv = o * ftanh_(cv);
            c_out[(size_t)bG * HID + jg] = cv;
            h_out[(size_t)bG * HID + jg] = hv;
            alog[(size_t)bG * KLOG + jg] = __float2half_rn(hv);
        }
    }
}

// ============================================================================
// Launch
// ============================================================================
extern "C" void kernel_launch(void* const* d_in, const int* in_sizes, int n_in,
                              void* d_out, int out_size)
{
    const float* x      = (const float*)d_in[0];
    const float* c_prev = (const float*)d_in[1];
    const float* h_prev = (const float*)d_in[2];
    const float* Wf     = (const float*)d_in[3];
    const float* bf     = (const float*)d_in[4];
    const float* Wu     = (const float*)d_in[5];
    const float* bu     = (const float*)d_in[6];
    const float* Wo     = (const float*)d_in[7];
    const float* bo     = (const float*)d_in[8];
    const float* Wc     = (const float*)d_in[9];
    const float* bc     = (const float*)d_in[10];
    const float* Wl     = (const float*)d_in[11];
    const float* bl     = (const float*)d_in[12];

    float* out   = (float*)d_out;
    float* c_out = out;
    float* h_out = out + (size_t)BATCH * HID;
    float* y_out = out + (size_t)2 * BATCH * HID;

    __half *blog, *alog, *bgate, *agate;
    cudaGetSymbolAddress((void**)&blog,  g_Blog);
    cudaGetSymbolAddress((void**)&alog,  g_Alog);
    cudaGetSymbolAddress((void**)&bgate, g_Bgate);
    cudaGetSymbolAddress((void**)&agate, g_Agate);

    // gates: BN=256, 512 threads, 1 CTA/SM, smem (128+256)*144*3 = 165888
    constexpr int SMEM_G = (128 + 256) * 144 * 3;
    // logits: BN=128, 256 threads, 2 CTAs/SM, smem (128+128)*144*3 = 110592
    constexpr int SMEM_L = (128 + 128) * 144 * 3;

    cudaFuncSetAttribute((const void*)gemm_f16<KGATE, 256, 512, 1, 1>,
                         cudaFuncAttributeMaxDynamicSharedMemorySize, SMEM_G);
    cudaFuncSetAttribute((const void*)gemm_f16<KLOG, 128, 256, 2, 0>,
                         cudaFuncAttributeMaxDynamicSharedMemorySize, SMEM_L);

    // 1) single merged pack launch
    pack_all<<<(PK_TOTAL + 255) / 256, 256>>>(Wf, Wu, Wo, Wc,
                                              x, c_prev, h_prev, Wl,
                                              bgate, agate, blog);

    // 2) gates GEMM with fused LSTM combine -> c_out, h_out, alog
    {
        dim3 g(1024 / 256, BATCH / T_BM);    // (4, 64)
        gemm_f16<KGATE, 256, 512, 1, 1><<<g, 512, SMEM_G>>>(
            agate, bgate, nullptr, nullptr, 0,
            c_prev, bf, bu, bo, bc, c_out, h_out, alog);
    }
    // 3) logits GEMM: y = alog . blog^T + bl   [8192, 32000]
    {
        dim3 g(VOCAB / 128, BATCH / T_BM);   // (250, 64)
        gemm_f16<KLOG, 128, 256, 2, 0><<<g, 256, SMEM_L>>>(
            alog, blog, bl, y_out, VOCAB,
            nullptr, nullptr, nullptr, nullptr, nullptr,
            nullptr, nullptr, nullptr);
    }
}